// round 1
// baseline (speedup 1.0000x reference)
#include <cuda_runtime.h>
#include <math.h>

// Problem constants
#define B_  4
#define T_  8
#define C_  256
#define NP  196
#define H_  4
#define S_  1568          // T_*NP
#define BH  16            // B_*H_
#define SC  401408        // S_*C_
#define SSI 2458624       // S_*S_

// ---------------- scratch (device globals; no allocation allowed) ----------
__device__ float g_x[B_ * SC];          // x = permuted emb; later reused as head-mean ctx
__device__ float g_Q[BH * SC];
__device__ float g_K[BH * SC];
__device__ float g_V[BH * SC];
__device__ float g_scr[16 * SSI];       // scores, softmaxed in place (157 MB)
__device__ float g_ctx[BH * SC];
__device__ float g_part[BH * 512 * 2];  // per-block partial sums (sum, sumsq)
__device__ float g_stats[BH * 2];       // mean, inv_std per (b,h)

// ---------------- permute: emb[B,T,C,N] -> x[B, S=T*N, C] ------------------
__global__ void permute_k(const float* __restrict__ emb, float* __restrict__ x)
{
    int i = blockIdx.x * blockDim.x + threadIdx.x;
    if (i >= B_ * S_ * C_) return;
    int c = i % C_;
    int r = i / C_;
    int n = r % NP;
    int t = (r / NP) % T_;
    int b = r / (NP * T_);
    x[i] = emb[(((size_t)(b * T_ + t) * C_) + c) * NP + n];
}

// ---------------- tiled SGEMM ----------------------------------------------
// C[z][m][n] = alpha * sum_k A[m][k] * B(n,k)
//   BT=true : B stored [n][k]   (NT gemm, K contiguous both sides)
//   BT=false: B stored [k][n]   (NN for the B operand)
// Batch offsets: Aoff=((z/dA)%mA)*sA, Boff=((z/dB)%mB)*sB, Coff=z*sC
// STATS: also write per-block (sum, sumsq) of the scaled outputs to part[].
#define BM 128
#define BN 64
#define BKK 16

template<bool BT, bool STATS>
__global__ __launch_bounds__(256, 2)
void gemm_k(const float* __restrict__ A, int lda, long long sA, int dA, int mA,
            const float* __restrict__ Bm, int ldb, long long sB, int dB, int mB,
            float* __restrict__ Cm, int ldc, long long sC,
            int M, int N, int K, float alpha, float* __restrict__ part)
{
    __shared__ float As[BKK][BM + 4];
    __shared__ float Bs[BKK][BN + 4];

    int z = blockIdx.z;
    const float* Ab = A  + (long long)((z / dA) % mA) * sA;
    const float* Bb = Bm + (long long)((z / dB) % mB) * sB;
    float*       Cb = Cm + (long long)z * sC;

    int tid = threadIdx.x;
    int tx = tid & 15, ty = tid >> 4;
    int m0 = blockIdx.y * BM, n0 = blockIdx.x * BN;

    float acc[8][4];
#pragma unroll
    for (int i = 0; i < 8; i++)
#pragma unroll
        for (int j = 0; j < 4; j++) acc[i][j] = 0.f;

    int arow = tid >> 2;
    int akq  = (tid & 3) << 2;

    for (int kt = 0; kt < K; kt += BKK) {
        // A tile: 128 x 16, K-contiguous, store transposed As[k][m]
#pragma unroll
        for (int l = 0; l < 2; l++) {
            int row = arow + l * 64;
            int gm = m0 + row;
            float4 f = make_float4(0.f, 0.f, 0.f, 0.f);
            if (gm < M) f = *(const float4*)(Ab + (size_t)gm * lda + kt + akq);
            As[akq + 0][row] = f.x; As[akq + 1][row] = f.y;
            As[akq + 2][row] = f.z; As[akq + 3][row] = f.w;
        }
        if (BT) {
            int nrow = tid >> 2;
            int kq = (tid & 3) << 2;
            int gn = n0 + nrow;
            float4 f = make_float4(0.f, 0.f, 0.f, 0.f);
            if (gn < N) f = *(const float4*)(Bb + (size_t)gn * ldb + kt + kq);
            Bs[kq + 0][nrow] = f.x; Bs[kq + 1][nrow] = f.y;
            Bs[kq + 2][nrow] = f.z; Bs[kq + 3][nrow] = f.w;
        } else {
            int k = tid >> 4;
            int n4 = (tid & 15) << 2;
            int gn = n0 + n4;
            float4 f = make_float4(0.f, 0.f, 0.f, 0.f);
            if (gn < N) f = *(const float4*)(Bb + (size_t)(kt + k) * ldb + gn);
            *(float4*)&Bs[k][n4] = f;
        }
        __syncthreads();
#pragma unroll
        for (int k = 0; k < BKK; k++) {
            float a[8], b[4];
            *(float4*)&a[0] = *(const float4*)&As[k][ty * 8];
            *(float4*)&a[4] = *(const float4*)&As[k][ty * 8 + 4];
            *(float4*)&b[0] = *(const float4*)&Bs[k][tx * 4];
#pragma unroll
            for (int i = 0; i < 8; i++)
#pragma unroll
                for (int j = 0; j < 4; j++)
                    acc[i][j] = fmaf(a[i], b[j], acc[i][j]);
        }
        __syncthreads();
    }

#pragma unroll
    for (int i = 0; i < 8; i++)
#pragma unroll
        for (int j = 0; j < 4; j++) acc[i][j] *= alpha;

    int gn = n0 + tx * 4;
#pragma unroll
    for (int i = 0; i < 8; i++) {
        int gm = m0 + ty * 8 + i;
        if (gm < M && gn < N) {
            float4 f = make_float4(acc[i][0], acc[i][1], acc[i][2], acc[i][3]);
            *(float4*)(Cb + (size_t)gm * ldc + gn) = f;
        }
    }

    if (STATS) {
        // OOB tile rows/cols computed from zero-padded smem -> acc==0, harmless.
        float s = 0.f, sq = 0.f;
#pragma unroll
        for (int i = 0; i < 8; i++)
#pragma unroll
            for (int j = 0; j < 4; j++) { float v = acc[i][j]; s += v; sq += v * v; }
        float* sred = &As[0][0];   // reuse smem (last sync already passed)
        sred[tid] = s; sred[256 + tid] = sq;
        __syncthreads();
        for (int off = 128; off > 0; off >>= 1) {
            if (tid < off) {
                sred[tid]       += sred[tid + off];
                sred[256 + tid] += sred[256 + tid + off];
            }
            __syncthreads();
        }
        if (tid == 0) {
            int ppz = gridDim.x * gridDim.y;
            int pidx = z * ppz + blockIdx.y * gridDim.x + blockIdx.x;
            part[2 * pidx]     = sred[0];
            part[2 * pidx + 1] = sred[256];
        }
    }
}

// ---------------- finalize mean / inv_std per (b,h) ------------------------
__global__ void stats_k(const float* __restrict__ part, int partPerZ,
                        float* __restrict__ stats)
{
    int z = blockIdx.x;
    int tid = threadIdx.x;
    float s = 0.f, sq = 0.f;
    for (int i = tid; i < partPerZ; i += 256) {
        s  += part[2 * (z * partPerZ + i)];
        sq += part[2 * (z * partPerZ + i) + 1];
    }
    __shared__ float sm[512];
    sm[tid] = s; sm[256 + tid] = sq;
    __syncthreads();
    for (int off = 128; off > 0; off >>= 1) {
        if (tid < off) { sm[tid] += sm[tid + off]; sm[256 + tid] += sm[256 + tid + off]; }
        __syncthreads();
    }
    if (tid == 0) {
        float inv_cnt = 1.f / (float)SSI;
        float mean = sm[0] * inv_cnt;
        float var  = sm[256] * inv_cnt - mean * mean;
        stats[2 * z]     = mean;
        stats[2 * z + 1] = rsqrtf(var + 1e-5f);
    }
}

// ---------------- fused instancenorm + softmax, one block per row ----------
__global__ __launch_bounds__(256)
void softmax_k(float* __restrict__ scr, const float* __restrict__ stats)
{
    int row = blockIdx.x;            // [0, BH*S)
    int bh = row / S_;
    float mean = stats[2 * bh], inv = stats[2 * bh + 1];
    float* p = scr + (size_t)row * S_;
    int tid = threadIdx.x;

    float v[7];
    float mx = -1e30f;
#pragma unroll
    for (int r = 0; r < 7; r++) {
        int idx = r * 256 + tid;
        float xv = (idx < S_) ? (p[idx] - mean) * inv : -1e30f;
        v[r] = xv;
        mx = fmaxf(mx, xv);
    }
    __shared__ float sm[256];
    sm[tid] = mx; __syncthreads();
    for (int off = 128; off > 0; off >>= 1) {
        if (tid < off) sm[tid] = fmaxf(sm[tid], sm[tid + off]);
        __syncthreads();
    }
    float rmax = sm[0];
    __syncthreads();
    float s = 0.f;
#pragma unroll
    for (int r = 0; r < 7; r++) {
        int idx = r * 256 + tid;
        float e = (idx < S_) ? __expf(v[r] - rmax) : 0.f;
        v[r] = e; s += e;
    }
    sm[tid] = s; __syncthreads();
    for (int off = 128; off > 0; off >>= 1) {
        if (tid < off) sm[tid] += sm[tid + off];
        __syncthreads();
    }
    float rinv = 1.f / sm[0];
#pragma unroll
    for (int r = 0; r < 7; r++) {
        int idx = r * 256 + tid;
        if (idx < S_) p[idx] = v[r] * rinv;
    }
}

// ---------------- head mean: ctx[B,H,S,C] -> xbuf[B,S,C] -------------------
__global__ void headmean_k(const float* __restrict__ ctx, float* __restrict__ out)
{
    int i = blockIdx.x * blockDim.x + threadIdx.x;
    if (i >= B_ * SC) return;
    int b = i / SC;
    int j = i - b * SC;
    const float* base = ctx + (size_t)b * 4 * SC + j;
    out[i] = 0.25f * (base[0] + base[SC] + base[2 * (size_t)SC] + base[3 * (size_t)SC]);
}

// ---------------- launch ----------------------------------------------------
extern "C" void kernel_launch(void* const* d_in, const int* in_sizes, int n_in,
                              void* d_out, int out_size)
{
    const float* emb = (const float*)d_in[0];
    const float* Wq  = (const float*)d_in[1];
    const float* Wk  = (const float*)d_in[2];
    const float* Wv  = (const float*)d_in[3];
    const float* Wo  = (const float*)d_in[4];
    float* out = (float*)d_out;

    float *x, *Q, *K, *V, *scr, *ctx, *part, *stats;
    cudaGetSymbolAddress((void**)&x,     g_x);
    cudaGetSymbolAddress((void**)&Q,     g_Q);
    cudaGetSymbolAddress((void**)&K,     g_K);
    cudaGetSymbolAddress((void**)&V,     g_V);
    cudaGetSymbolAddress((void**)&scr,   g_scr);
    cudaGetSymbolAddress((void**)&ctx,   g_ctx);
    cudaGetSymbolAddress((void**)&part,  g_part);
    cudaGetSymbolAddress((void**)&stats, g_stats);

    // 1) permute emb -> x [B,S,C]
    permute_k<<<(B_ * S_ * C_ + 255) / 256, 256>>>(emb, x);

    // 2) QKV projections: out[z=b*4+h] = x[b] @ W[h]^T   (NT, batch 16 each)
    dim3 gq(C_ / BN, (S_ + BM - 1) / BM, BH);
    gemm_k<true, false><<<gq, 256>>>(x, C_, (long long)SC, 4, 4,
                                     Wq, C_, (long long)C_ * C_, 1, 4,
                                     Q, C_, (long long)SC,
                                     S_, C_, C_, 1.f, nullptr);
    gemm_k<true, false><<<gq, 256>>>(x, C_, (long long)SC, 4, 4,
                                     Wk, C_, (long long)C_ * C_, 1, 4,
                                     K, C_, (long long)SC,
                                     S_, C_, C_, 1.f, nullptr);
    gemm_k<true, false><<<gq, 256>>>(x, C_, (long long)SC, 4, 4,
                                     Wv, C_, (long long)C_ * C_, 1, 4,
                                     V, C_, (long long)SC,
                                     S_, C_, C_, 1.f, nullptr);

    // 3) scores = Q K^T / sqrt(S)  (NT) with fused sum/sumsq partials
    dim3 gs((S_ + BN - 1) / BN, (S_ + BM - 1) / BM, BH);
    float alpha = 1.0f / sqrtf((float)S_);
    gemm_k<true, true><<<gs, 256>>>(Q, C_, (long long)SC, 1, 16,
                                    K, C_, (long long)SC, 1, 16,
                                    scr, S_, (long long)SSI,
                                    S_, S_, C_, alpha, part);

    // 4) finalize mean/inv_std, then fused instancenorm+softmax per row
    stats_k<<<BH, 256>>>(part, gs.x * gs.y, stats);
    softmax_k<<<BH * S_, 256>>>(scr, stats);

    // 5) ctx = P @ V  (B operand is [k][n] -> NN)
    dim3 gc(C_ / BN, (S_ + BM - 1) / BM, BH);
    gemm_k<false, false><<<gc, 256>>>(scr, S_, (long long)SSI, 1, 16,
                                      V, C_, (long long)SC, 1, 16,
                                      ctx, C_, (long long)SC,
                                      S_, C_, S_, 1.f, nullptr);

    // 6) mean over heads -> reuse x buffer
    headmean_k<<<(B_ * SC + 255) / 256, 256>>>(ctx, x);

    // 7) out = ctx_mean @ Wo^T  (NT, batch B, shared weight)
    dim3 go(C_ / BN, (S_ + BM - 1) / BM, B_);
    gemm_k<true, false><<<go, 256>>>(x, C_, (long long)SC, 1, 4,
                                     Wo, C_, 0LL, 1, 1,
                                     out, C_, (long long)SC,
                                     S_, C_, C_, 1.f, nullptr);
}